// round 11
// baseline (speedup 1.0000x reference)
#include <cuda_runtime.h>
#include <cstdint>

// Problem constants
#define NLAT   8192
#define NSMP   2048
#define ES     64
#define EA     32
#define FARK   64
#define TPB    256
#define SCHUNK (NSMP / TPB)     // 8 sample chunks
#define NSL_S  45               // latent slices, states
#define NSL_A  25               // latent slices, actions
#define NSL_Z  4                // size-loss block rows
// 8*(45+25+4) = 592 blocks = exactly 2 waves at occupancy 2
#define FLT_BIG 3.402823466e+38f
#define NPOST  16               // post kernel blocks (8 chunks x 2 tensors)

// ---------------- scratch (device globals; no allocation allowed) ----------
__device__ float g_pt4_s[NSL_S * NSMP * 4];   // [slice][sample][4]
__device__ float g_pt4_a[NSL_A * NSMP * 4];
__device__ float g_tail[2][NSMP];
__device__ float g_sq[2][NSMP];
__device__ float g_size_part[NSL_Z * 8];
__device__ float g_red[NPOST];
__device__ int   g_arr[2][SCHUNK];            // per-(tensor,chunk) arrival counters
__device__ int   g_done2;

// branchless sorted insert: keep m0<=m1<=m2<=m3 smallest
__device__ __forceinline__ void ins4(float d, float& m0, float& m1, float& m2, float& m3) {
    float lo, hi;
    lo = fminf(m0, d);  hi = fmaxf(m0, d);  m0 = lo;
    lo = fminf(m1, hi); hi = fmaxf(m1, hi); m1 = lo;
    lo = fminf(m2, hi); hi = fmaxf(m2, hi); m2 = lo;
    m3 = fminf(m3, hi);
}

// ---------------- size loss partials (runs inside the cov launch) ----------
template<int E>
__device__ __forceinline__ float size_accum(const float* __restrict__ lat, int r0, int nrows, int tid) {
    float acc = 0.0f;
    for (int r = r0 + tid; r < r0 + nrows; r += TPB) {
        const float* row = lat + r * E;
        float a0 = 0.f, a1 = 0.f, a2 = 0.f, a3 = 0.f;
        #pragma unroll
        for (int k = 0; k < E; k += 4) {
            float4 v = *(const float4*)(row + k);
            a0 += fabsf(v.x); a1 += fabsf(v.y); a2 += fabsf(v.z); a3 += fabsf(v.w);
        }
        float n = (a0 + a1) + (a2 + a3);
        float viol = fmaxf(n - 1.0f, 0.0f);
        acc += viol * viol;
    }
    return acc;
}

__device__ void size_body(const float* __restrict__ lat_s,
                          const float* __restrict__ lat_a, int b, float* red) {
    const int tid = threadIdx.x;
    float acc = (b < 16) ? size_accum<ES>(lat_s, b * 512, 512, tid)
                         : size_accum<EA>(lat_a, (b - 16) * 512, 512, tid);
    red[tid] = acc;
    __syncthreads();
    for (int st = TPB / 2; st > 0; st >>= 1) {
        if (tid < st) red[tid] += red[tid + st];
        __syncthreads();
    }
    if (tid == 0) g_size_part[b] = red[0];
}

// ---------------- coverage partial top-4 (FFMA-imm, latent-pair unroll) ----
// d  = fmaf(lat, -0.5, q*0.5);  acc = fmaf(|d|, 2.0, acc)  -> FFMA-imm rt=1
// Exact rescale: fl((q-l)/2)*2 == fl(q-l); bit-identical to FADD chain.
template<int E, int TN, int NSL>
__device__ __forceinline__ void cov_body(const float* __restrict__ samples,
                                         const float* __restrict__ latents,
                                         int slice, float* tile, float* out4,
                                         int sel) {
    const int tid   = threadIdx.x;
    const int chunk = blockIdx.x;
    const int s     = chunk * TPB + tid;

    constexpr int base = NLAT / NSL;
    constexpr int rem  = NLAT % NSL;
    const int start = slice * base + (slice < rem ? slice : rem);
    const int len   = base + (slice < rem ? 1 : 0);

    float qh[E];
    #pragma unroll
    for (int k = 0; k < E; k += 4) {
        float4 v = *(const float4*)(samples + s * E + k);
        qh[k] = 0.5f * v.x; qh[k + 1] = 0.5f * v.y;
        qh[k + 2] = 0.5f * v.z; qh[k + 3] = 0.5f * v.w;
    }

    float m0 = FLT_BIG, m1 = FLT_BIG, m2 = FLT_BIG, m3 = FLT_BIG;

    for (int t0 = 0; t0 < len; t0 += TN) {
        const int tn = (len - t0 < TN) ? (len - t0) : TN;
        __syncthreads();
        const float4* src = (const float4*)(latents + (start + t0) * E);
        float4* dst = (float4*)tile;
        for (int i = tid; i < tn * (E / 4); i += TPB) dst[i] = src[i];
        __syncthreads();

        int n = 0;
        #pragma unroll 1
        for (; n + 2 <= tn; n += 2) {
            const float4* lrA = (const float4*)(tile + n * E);
            const float4* lrB = (const float4*)(tile + (n + 1) * E);
            float a0 = 0.f, a1 = 0.f, a2 = 0.f, a3 = 0.f;
            float b0 = 0.f, b1 = 0.f, b2 = 0.f, b3 = 0.f;
            #pragma unroll
            for (int k = 0; k < E / 4; k++) {
                float4 va = lrA[k];
                float d0 = fmaf(va.x, -0.5f, qh[4 * k]);
                float d1 = fmaf(va.y, -0.5f, qh[4 * k + 1]);
                float d2 = fmaf(va.z, -0.5f, qh[4 * k + 2]);
                float d3 = fmaf(va.w, -0.5f, qh[4 * k + 3]);
                a0 = fmaf(fabsf(d0), 2.0f, a0);
                a1 = fmaf(fabsf(d1), 2.0f, a1);
                a2 = fmaf(fabsf(d2), 2.0f, a2);
                a3 = fmaf(fabsf(d3), 2.0f, a3);
                float4 vb = lrB[k];
                float e0 = fmaf(vb.x, -0.5f, qh[4 * k]);
                float e1 = fmaf(vb.y, -0.5f, qh[4 * k + 1]);
                float e2 = fmaf(vb.z, -0.5f, qh[4 * k + 2]);
                float e3 = fmaf(vb.w, -0.5f, qh[4 * k + 3]);
                b0 = fmaf(fabsf(e0), 2.0f, b0);
                b1 = fmaf(fabsf(e1), 2.0f, b1);
                b2 = fmaf(fabsf(e2), 2.0f, b2);
                b3 = fmaf(fabsf(e3), 2.0f, b3);
            }
            ins4((a0 + a1) + (a2 + a3), m0, m1, m2, m3);
            ins4((b0 + b1) + (b2 + b3), m0, m1, m2, m3);
        }
        if (n < tn) {   // odd epilogue
            const float4* lr = (const float4*)(tile + n * E);
            float a0 = 0.f, a1 = 0.f, a2 = 0.f, a3 = 0.f;
            #pragma unroll
            for (int k = 0; k < E / 4; k++) {
                float4 v = lr[k];
                float d0 = fmaf(v.x, -0.5f, qh[4 * k]);
                float d1 = fmaf(v.y, -0.5f, qh[4 * k + 1]);
                float d2 = fmaf(v.z, -0.5f, qh[4 * k + 2]);
                float d3 = fmaf(v.w, -0.5f, qh[4 * k + 3]);
                a0 = fmaf(fabsf(d0), 2.0f, a0);
                a1 = fmaf(fabsf(d1), 2.0f, a1);
                a2 = fmaf(fabsf(d2), 2.0f, a2);
                a3 = fmaf(fabsf(d3), 2.0f, a3);
            }
            ins4((a0 + a1) + (a2 + a3), m0, m1, m2, m3);
        }
    }
    *(float4*)(out4 + (slice * NSMP + s) * 4) = make_float4(m0, m1, m2, m3);

    // ---- last-arrival merge for this (tensor, chunk): overlapped ----------
    __threadfence();          // make partial visible before arrival
    __syncthreads();          // whole block's stores done
    __shared__ int s_last;
    if (tid == 0)
        s_last = (atomicAdd(&g_arr[sel][chunk], 1) == NSL - 1);
    __syncthreads();
    if (s_last) {
        if (tid == 0) g_arr[sel][chunk] = 0;   // reset for next graph replay
        __threadfence();                        // acquire: see all partials
        float M0 = FLT_BIG, M1 = FLT_BIG, M2 = FLT_BIG, M3 = FLT_BIG;
        for (int k = 0; k < NSL; k++) {
            float4 v = *(const float4*)(out4 + ((size_t)k * NSMP + s) * 4);
            ins4(v.x, M0, M1, M2, M3);
            ins4(v.y, M0, M1, M2, M3);
            ins4(v.z, M0, M1, M2, M3);
            ins4(v.w, M0, M1, M2, M3);
        }
        g_tail[sel][s] = 0.25f * ((M0 + M1) + (M2 + M3));
        g_sq[sel][s]   = (M0 * M0 + M1 * M1) + (M2 * M2 + M3 * M3);
    }
}

// grid: (SCHUNK, NSL_S + NSL_A + NSL_Z)
__global__ void __launch_bounds__(TPB, 2)
cov_partial_kernel(const float* __restrict__ smp_s, const float* __restrict__ lat_s,
                   const float* __restrict__ smp_a, const float* __restrict__ lat_a) {
    __shared__ __align__(16) float tile[8192];   // 32 KB
    const int y = blockIdx.y;
    if (y < NSL_S)
        cov_body<ES, 128, NSL_S>(smp_s, lat_s, y, tile, g_pt4_s, 0);
    else if (y < NSL_S + NSL_A)
        cov_body<EA, 256, NSL_A>(smp_a, lat_a, y - NSL_S, tile, g_pt4_a, 1);
    else
        size_body(lat_s, lat_a, (y - NSL_S - NSL_A) * 8 + blockIdx.x, tile);
}

// ---------------- post: rank + select + combine (one small kernel) ---------
// grid (SCHUNK, 2) = 16 blocks. tails/sq already computed by cov launch.
__global__ void post_kernel(float* __restrict__ out) {
    __shared__ __align__(16) float tl[NSMP];
    __shared__ float red[TPB];
    const int sel = blockIdx.y;
    const int tid = threadIdx.x;
    const int s   = blockIdx.x * TPB + tid;

    for (int i = tid; i < NSMP; i += TPB) tl[i] = g_tail[sel][i];
    __syncthreads();

    const int ti = __float_as_int(tl[s]);   // positive floats: int order == fp order
    int cnt = 0;
    #pragma unroll 4
    for (int j = 0; j < NSMP; j += 4) {
        float4 v = *(const float4*)(tl + j);
        cnt += (__float_as_int(v.x) > ti) || (__float_as_int(v.x) == ti && (j)     < s);
        cnt += (__float_as_int(v.y) > ti) || (__float_as_int(v.y) == ti && (j + 1) < s);
        cnt += (__float_as_int(v.z) > ti) || (__float_as_int(v.z) == ti && (j + 2) < s);
        cnt += (__float_as_int(v.w) > ti) || (__float_as_int(v.w) == ti && (j + 3) < s);
    }
    red[tid] = (cnt < FARK) ? g_sq[sel][s] : 0.0f;
    __syncthreads();
    for (int st = TPB / 2; st > 0; st >>= 1) {
        if (tid < st) red[tid] += red[tid + st];
        __syncthreads();
    }

    if (tid == 0) {
        g_red[sel * SCHUNK + blockIdx.x] = red[0];
        __threadfence();
        if (atomicAdd(&g_done2, 1) == NPOST - 1) {
            float r = 0.f;
            #pragma unroll
            for (int b = 0; b < NPOST; b++) r += g_red[b];
            float ss = 0.f, sa = 0.f;
            #pragma unroll
            for (int b = 0; b < 16; b++)  ss += g_size_part[b];
            #pragma unroll
            for (int b = 16; b < 32; b++) sa += g_size_part[b];
            out[0] = ss / (float)NLAT + sa / (float)NLAT + r / (float)(FARK * 4);
            g_done2 = 0;              // reset for next graph replay
            __threadfence();
        }
    }
}

// ---------------- launch ----------------------------------------------------
extern "C" void kernel_launch(void* const* d_in, const int* in_sizes, int n_in,
                              void* d_out, int out_size) {
    const float* lat_s = (const float*)d_in[0];   // latent_states   [8192,64]
    const float* lat_a = (const float*)d_in[1];   // latent_actions  [8192,32]
    const float* smp_s = (const float*)d_in[2];   // state samples   [2048,64]
    const float* smp_a = (const float*)d_in[3];   // action samples  [2048,32]
    float* out = (float*)d_out;

    cov_partial_kernel<<<dim3(SCHUNK, NSL_S + NSL_A + NSL_Z), TPB>>>(smp_s, lat_s, smp_a, lat_a);
    post_kernel<<<dim3(SCHUNK, 2), TPB>>>(out);
}

// round 12
// speedup vs baseline: 1.1333x; 1.1333x over previous
#include <cuda_runtime.h>
#include <cstdint>

// Problem constants
#define NLAT   8192
#define NSMP   2048
#define ES     64
#define EA     32
#define FARK   64
#define TPB    256
#define SCHUNK (NSMP / TPB)     // 8 sample chunks
#define NSL_S  45               // latent slices, states
#define NSL_A  25               // latent slices, actions
#define NSL_Z  4                // size-loss block rows
// 8*(45+25+4) = 592 blocks = exactly 2 waves at occupancy 2
#define FLT_BIG 3.402823466e+38f
#define NRANK  (SCHUNK * 2 * 16)   // 256 rank blocks

// ---------------- scratch (device globals; no allocation allowed) ----------
__device__ float g_pt4_s[NSL_S * NSMP * 4];   // [slice][sample][4]
__device__ float g_pt4_a[NSL_A * NSMP * 4];
__device__ float g_tail[2][NSMP];
__device__ float g_sq[2][NSMP];
__device__ int   g_cnt[2][NSMP];
__device__ float g_size_part[NSL_Z * 8];
__device__ int   g_done2;

// branchless sorted insert: keep m0<=m1<=m2<=m3 smallest
__device__ __forceinline__ void ins4(float d, float& m0, float& m1, float& m2, float& m3) {
    float lo, hi;
    lo = fminf(m0, d);  hi = fmaxf(m0, d);  m0 = lo;
    lo = fminf(m1, hi); hi = fmaxf(m1, hi); m1 = lo;
    lo = fminf(m2, hi); hi = fmaxf(m2, hi); m2 = lo;
    m3 = fminf(m3, hi);
}

// ---------------- size loss partials (runs inside the cov launch) ----------
template<int E>
__device__ __forceinline__ float size_accum(const float* __restrict__ lat, int r0, int nrows, int tid) {
    float acc = 0.0f;
    for (int r = r0 + tid; r < r0 + nrows; r += TPB) {
        const float* row = lat + r * E;
        float a0 = 0.f, a1 = 0.f, a2 = 0.f, a3 = 0.f;
        #pragma unroll
        for (int k = 0; k < E; k += 4) {
            float4 v = *(const float4*)(row + k);
            a0 += fabsf(v.x); a1 += fabsf(v.y); a2 += fabsf(v.z); a3 += fabsf(v.w);
        }
        float n = (a0 + a1) + (a2 + a3);
        float viol = fmaxf(n - 1.0f, 0.0f);
        acc += viol * viol;
    }
    return acc;
}

__device__ void size_body(const float* __restrict__ lat_s,
                          const float* __restrict__ lat_a, int b, float* red) {
    const int tid = threadIdx.x;
    float acc = (b < 16) ? size_accum<ES>(lat_s, b * 512, 512, tid)
                         : size_accum<EA>(lat_a, (b - 16) * 512, 512, tid);
    red[tid] = acc;
    __syncthreads();
    for (int st = TPB / 2; st > 0; st >>= 1) {
        if (tid < st) red[tid] += red[tid + st];
        __syncthreads();
    }
    if (tid == 0) g_size_part[b] = red[0];
}

// ---------------- coverage partial top-4 (FFMA-imm, latent-pair unroll) ----
// d  = fmaf(lat, -0.5, q*0.5);  acc = fmaf(|d|, 2.0, acc)  -> FFMA-imm rt=1
// Exact rescale: fl((q-l)/2)*2 == fl(q-l); bit-identical to FADD chain.
template<int E, int TN, int NSL>
__device__ __forceinline__ void cov_body(const float* __restrict__ samples,
                                         const float* __restrict__ latents,
                                         int slice, float* tile, float* out4) {
    const int tid = threadIdx.x;
    const int s   = blockIdx.x * TPB + tid;

    constexpr int base = NLAT / NSL;
    constexpr int rem  = NLAT % NSL;
    const int start = slice * base + (slice < rem ? slice : rem);
    const int len   = base + (slice < rem ? 1 : 0);

    float qh[E];
    #pragma unroll
    for (int k = 0; k < E; k += 4) {
        float4 v = *(const float4*)(samples + s * E + k);
        qh[k] = 0.5f * v.x; qh[k + 1] = 0.5f * v.y;
        qh[k + 2] = 0.5f * v.z; qh[k + 3] = 0.5f * v.w;
    }

    float m0 = FLT_BIG, m1 = FLT_BIG, m2 = FLT_BIG, m3 = FLT_BIG;

    for (int t0 = 0; t0 < len; t0 += TN) {
        const int tn = (len - t0 < TN) ? (len - t0) : TN;
        __syncthreads();
        const float4* src = (const float4*)(latents + (start + t0) * E);
        float4* dst = (float4*)tile;
        for (int i = tid; i < tn * (E / 4); i += TPB) dst[i] = src[i];
        __syncthreads();

        int n = 0;
        #pragma unroll 1
        for (; n + 2 <= tn; n += 2) {
            const float4* lrA = (const float4*)(tile + n * E);
            const float4* lrB = (const float4*)(tile + (n + 1) * E);
            float a0 = 0.f, a1 = 0.f, a2 = 0.f, a3 = 0.f;
            float b0 = 0.f, b1 = 0.f, b2 = 0.f, b3 = 0.f;
            #pragma unroll
            for (int k = 0; k < E / 4; k++) {
                float4 va = lrA[k];
                float d0 = fmaf(va.x, -0.5f, qh[4 * k]);
                float d1 = fmaf(va.y, -0.5f, qh[4 * k + 1]);
                float d2 = fmaf(va.z, -0.5f, qh[4 * k + 2]);
                float d3 = fmaf(va.w, -0.5f, qh[4 * k + 3]);
                a0 = fmaf(fabsf(d0), 2.0f, a0);
                a1 = fmaf(fabsf(d1), 2.0f, a1);
                a2 = fmaf(fabsf(d2), 2.0f, a2);
                a3 = fmaf(fabsf(d3), 2.0f, a3);
                float4 vb = lrB[k];
                float e0 = fmaf(vb.x, -0.5f, qh[4 * k]);
                float e1 = fmaf(vb.y, -0.5f, qh[4 * k + 1]);
                float e2 = fmaf(vb.z, -0.5f, qh[4 * k + 2]);
                float e3 = fmaf(vb.w, -0.5f, qh[4 * k + 3]);
                b0 = fmaf(fabsf(e0), 2.0f, b0);
                b1 = fmaf(fabsf(e1), 2.0f, b1);
                b2 = fmaf(fabsf(e2), 2.0f, b2);
                b3 = fmaf(fabsf(e3), 2.0f, b3);
            }
            ins4((a0 + a1) + (a2 + a3), m0, m1, m2, m3);
            ins4((b0 + b1) + (b2 + b3), m0, m1, m2, m3);
        }
        if (n < tn) {   // odd epilogue
            const float4* lr = (const float4*)(tile + n * E);
            float a0 = 0.f, a1 = 0.f, a2 = 0.f, a3 = 0.f;
            #pragma unroll
            for (int k = 0; k < E / 4; k++) {
                float4 v = lr[k];
                float d0 = fmaf(v.x, -0.5f, qh[4 * k]);
                float d1 = fmaf(v.y, -0.5f, qh[4 * k + 1]);
                float d2 = fmaf(v.z, -0.5f, qh[4 * k + 2]);
                float d3 = fmaf(v.w, -0.5f, qh[4 * k + 3]);
                a0 = fmaf(fabsf(d0), 2.0f, a0);
                a1 = fmaf(fabsf(d1), 2.0f, a1);
                a2 = fmaf(fabsf(d2), 2.0f, a2);
                a3 = fmaf(fabsf(d3), 2.0f, a3);
            }
            ins4((a0 + a1) + (a2 + a3), m0, m1, m2, m3);
        }
    }
    *(float4*)(out4 + (slice * NSMP + s) * 4) = make_float4(m0, m1, m2, m3);
}

// grid: (SCHUNK, NSL_S + NSL_A + NSL_Z)
__global__ void __launch_bounds__(TPB, 2)
cov_partial_kernel(const float* __restrict__ smp_s, const float* __restrict__ lat_s,
                   const float* __restrict__ smp_a, const float* __restrict__ lat_a) {
    __shared__ __align__(16) float tile[8192];   // 32 KB
    const int y = blockIdx.y;
    if (y < NSL_S)
        cov_body<ES, 128, NSL_S>(smp_s, lat_s, y, tile, g_pt4_s);
    else if (y < NSL_S + NSL_A)
        cov_body<EA, 256, NSL_A>(smp_a, lat_a, y - NSL_S, tile, g_pt4_a);
    else
        size_body(lat_s, lat_a, (y - NSL_S - NSL_A) * 8 + blockIdx.x, tile);
}

// ---------------- merge partial top-4 across slices ------------------------
// 4 threads per sample, shfl combine. grid: (NSMP/64, 2)
__global__ void cov_merge_kernel() {
    const int sel = blockIdx.y;
    const int tid = threadIdx.x;
    const int s   = blockIdx.x * 64 + (tid >> 2);
    const int sub = tid & 3;
    const int nsl = sel ? NSL_A : NSL_S;
    const float* base = sel ? g_pt4_a : g_pt4_s;

    float m0 = FLT_BIG, m1 = FLT_BIG, m2 = FLT_BIG, m3 = FLT_BIG;
    for (int k = sub; k < nsl; k += 4) {
        float4 v = *(const float4*)(base + (k * NSMP + s) * 4);
        ins4(v.x, m0, m1, m2, m3);
        ins4(v.y, m0, m1, m2, m3);
        ins4(v.z, m0, m1, m2, m3);
        ins4(v.w, m0, m1, m2, m3);
    }
    #pragma unroll
    for (int off = 2; off >= 1; off >>= 1) {
        float n0 = __shfl_down_sync(0xffffffffu, m0, off);
        float n1 = __shfl_down_sync(0xffffffffu, m1, off);
        float n2 = __shfl_down_sync(0xffffffffu, m2, off);
        float n3 = __shfl_down_sync(0xffffffffu, m3, off);
        ins4(n0, m0, m1, m2, m3);
        ins4(n1, m0, m1, m2, m3);
        ins4(n2, m0, m1, m2, m3);
        ins4(n3, m0, m1, m2, m3);
    }
    if (sub == 0) {
        g_tail[sel][s] = 0.25f * ((m0 + m1) + (m2 + m3));
        g_sq[sel][s]   = (m0 * m0 + m1 * m1) + (m2 * m2 + m3 * m3);
        g_cnt[sel][s]  = 0;
    }
}

// ---------------- rank counts + last-block combine -------------------------
// grid (SCHUNK, 2, 16): z splits j into 128-chunks; int atomic partial counts.
// The LAST-arriving block performs the final fixed-order combine on its warm
// SM (replaces the former 13us cold grid=1 combine kernel).
__global__ void rank_kernel(float* __restrict__ out) {
    __shared__ __align__(16) float tj_s[128];
    __shared__ int s_last;
    const int sel = blockIdx.y, tid = threadIdx.x;
    const int jbase = blockIdx.z * 128;
    if (tid < 128) tj_s[tid] = g_tail[sel][jbase + tid];
    __syncthreads();
    const int i  = blockIdx.x * TPB + tid;
    const int ti = __float_as_int(g_tail[sel][i]);   // positive: int order == fp order
    int cnt = 0;
    #pragma unroll
    for (int jj = 0; jj < 128; jj += 4) {
        float4 v = *(const float4*)(tj_s + jj);
        cnt += (__float_as_int(v.x) > ti) || (__float_as_int(v.x) == ti && (jbase + jj)     < i);
        cnt += (__float_as_int(v.y) > ti) || (__float_as_int(v.y) == ti && (jbase + jj + 1) < i);
        cnt += (__float_as_int(v.z) > ti) || (__float_as_int(v.z) == ti && (jbase + jj + 2) < i);
        cnt += (__float_as_int(v.w) > ti) || (__float_as_int(v.w) == ti && (jbase + jj + 3) < i);
    }
    if (cnt) atomicAdd(&g_cnt[sel][i], cnt);

    // ---- last-arrival combine ----
    __threadfence();            // release this block's atomics
    __syncthreads();
    if (tid == 0)
        s_last = (atomicAdd(&g_done2, 1) == NRANK - 1);
    __syncthreads();
    if (s_last) {
        if (tid == 0) { g_done2 = 0; }          // reset for next graph replay
        __threadfence();                        // acquire: see all blocks' atomics
        __shared__ float red[8];
        float acc = 0.0f;
        #pragma unroll
        for (int r = 0; r < NSMP / TPB; r++) {
            int k = r * TPB + tid;
            float v0 = (g_cnt[0][k] < FARK) ? g_sq[0][k] : 0.0f;
            float v1 = (g_cnt[1][k] < FARK) ? g_sq[1][k] : 0.0f;
            acc += v0 + v1;
        }
        #pragma unroll
        for (int off = 16; off; off >>= 1) acc += __shfl_down_sync(0xffffffffu, acc, off);
        if ((tid & 31) == 0) red[tid >> 5] = acc;
        __syncthreads();
        if (tid == 0) {
            float r8 = 0.f;
            #pragma unroll
            for (int w = 0; w < 8; w++) r8 += red[w];
            float ss = 0.f, sa = 0.f;
            #pragma unroll
            for (int b = 0; b < 16; b++)  ss += g_size_part[b];
            #pragma unroll
            for (int b = 16; b < 32; b++) sa += g_size_part[b];
            out[0] = ss / (float)NLAT + sa / (float)NLAT + r8 / (float)(FARK * 4);
        }
    }
}

// ---------------- launch ----------------------------------------------------
extern "C" void kernel_launch(void* const* d_in, const int* in_sizes, int n_in,
                              void* d_out, int out_size) {
    const float* lat_s = (const float*)d_in[0];   // latent_states   [8192,64]
    const float* lat_a = (const float*)d_in[1];   // latent_actions  [8192,32]
    const float* smp_s = (const float*)d_in[2];   // state samples   [2048,64]
    const float* smp_a = (const float*)d_in[3];   // action samples  [2048,32]
    float* out = (float*)d_out;

    cov_partial_kernel<<<dim3(SCHUNK, NSL_S + NSL_A + NSL_Z), TPB>>>(smp_s, lat_s, smp_a, lat_a);
    cov_merge_kernel<<<dim3(NSMP / 64, 2), TPB>>>();
    rank_kernel<<<dim3(SCHUNK, 2, 16), TPB>>>(out);
}